// round 17
// baseline (speedup 1.0000x reference)
#include <cuda_runtime.h>
#include <cuda_bf16.h>

#define INPUT_DIM 4
#define H1 64
#define H2 32
#define BATCH 64
#define SEQ 4096
#define NTHREADS 256

typedef unsigned long long ull;

// ---- packed f32x2 helpers ----
__device__ __forceinline__ ull pk2(float a, float b) {
    ull r; asm("mov.b64 %0, {%1, %2};" : "=l"(r) : "f"(a), "f"(b)); return r;
}
__device__ __forceinline__ void upk2(ull v, float& a, float& b) {
    asm("mov.b64 {%0, %1}, %2;" : "=f"(a), "=f"(b) : "l"(v));
}
__device__ __forceinline__ ull fma2(ull a, ull b, ull c) {
    ull d; asm("fma.rn.f32x2 %0, %1, %2, %3;" : "=l"(d) : "l"(a), "l"(b), "l"(c)); return d;
}
__device__ __forceinline__ ull add2(ull a, ull b) {
    ull d; asm("add.rn.f32x2 %0, %1, %2;" : "=l"(d) : "l"(a), "l"(b)); return d;
}
__device__ __forceinline__ float tanh_approx(float x) {
    float y; asm("tanh.approx.f32 %0, %1;" : "=f"(y) : "f"(x)); return y;
}

__global__ void __launch_bounds__(NTHREADS, 1)
lstm2_kernel(const float* __restrict__ x,
             const float* __restrict__ W_ih1, const float* __restrict__ W_hh1,
             const float* __restrict__ b_ih1, const float* __restrict__ b_hh1,
             const float* __restrict__ W_ih2, const float* __restrict__ W_hh2,
             const float* __restrict__ b_ih2, const float* __restrict__ b_hh2,
             float* __restrict__ out)
{
    const int b   = blockIdx.x;
    const int tid = threadIdx.x;

    __shared__ __align__(16) float h1buf[2][H1];   // double buffer: slot t&1 = h1(t)
    __shared__ __align__(16) float h2buf[2][H2];   // slot (s+1)&1 = h2(s)

    // ---------------- L1 role: 1 gate per thread ----------------
    // u1 = tid>>2, q1 = tid&3 (i,f,g,o). Gate gather via shfl 1/2/3 to q1==0.
    const int u1 = tid >> 2;
    const int q1 = tid & 3;
    const float sc1   = (q1 == 2) ? 1.0f : 0.5f;   // prescale (sigmoid via 0.5*tanh(0.5x)+0.5)
    const float actA1 = (q1 == 2) ? 1.0f : 0.5f;
    const float actB1 = (q1 == 2) ? 0.0f : 0.5f;

    ull w1[32], xw0, xw1;
    {
        const int row = q1 * H1 + u1;
        const float2* whh = reinterpret_cast<const float2*>(W_hh1 + row * H1);
        #pragma unroll
        for (int k = 0; k < 32; ++k) {
            const float2 v = whh[k]; w1[k] = pk2(sc1 * v.x, sc1 * v.y);
        }
        const float2* wih = reinterpret_cast<const float2*>(W_ih1 + row * INPUT_DIM);
        float2 v;
        v = wih[0]; xw0 = pk2(sc1 * v.x, sc1 * v.y);
        v = wih[1]; xw1 = pk2(sc1 * v.x, sc1 * v.y);
    }
    ull bias1p;
    {
        const int row = q1 * H1 + u1;
        bias1p = pk2(sc1 * (b_ih1[row] + b_hh1[row]), 0.0f);
    }

    // ---------------- L2 role: half-gate per thread ----------------
    // gs = tid>>1 (gate slot 0..127), half = tid&1; u2g = gs>>2, q2 = gs&3.
    // 8-lane group per unit: combine halves via shfl^1, gates via shfl^2/4/6.
    const int gs   = tid >> 1;
    const int half = tid & 1;
    const int q2   = gs & 3;
    const int u2g  = gs >> 2;
    const float sc2   = (q2 == 2) ? 1.0f : 0.5f;
    const float actA2 = (q2 == 2) ? 1.0f : 0.5f;
    const float actB2 = (q2 == 2) ? 0.0f : 0.5f;

    ull w2a[16], w2b[8];
    {
        const int row = q2 * H2 + u2g;
        const float2* wih = reinterpret_cast<const float2*>(W_ih2 + row * H1 + half * 32);
        #pragma unroll
        for (int k = 0; k < 16; ++k) {
            const float2 v = wih[k]; w2a[k] = pk2(sc2 * v.x, sc2 * v.y);
        }
        const float2* whh = reinterpret_cast<const float2*>(W_hh2 + row * H2 + half * 16);
        #pragma unroll
        for (int k = 0; k < 8; ++k) {
            const float2 v = whh[k]; w2b[k] = pk2(sc2 * v.x, sc2 * v.y);
        }
    }
    ull bias2p;
    {
        const int row = q2 * H2 + u2g;
        bias2p = half ? 0ull : pk2(sc2 * (b_ih2[row] + b_hh2[row]), 0.0f);
    }

    // init: h1(-1)=0 in slot 1 (read at t=0 as slot (0-1)&1=1); h2(-1)=0 in buf 0
    if (q1 == 0) h1buf[1][u1] = 0.0f;
    if (tid < H2) h2buf[0][tid] = 0.0f;
    __syncthreads();

    float c1 = 0.0f;   // valid in q1==0 lanes
    float c2 = 0.0f;   // valid in (tid&7)==0 lanes

    const float4* xb4 = reinterpret_cast<const float4*>(x + (size_t)b * SEQ * INPUT_DIM);
    float* outb = out + (size_t)b * SEQ * H2;

    float4 xv  = __ldg(xb4);         // x(0)
    float4 xv1 = __ldg(xb4 + 1);     // x(1)

    // iteration t: L1 computes h1(t) (t<SEQ); L2 computes h2(t-1) (t>=1); one bar.
    #pragma unroll 1
    for (int t = 0; t <= SEQ; ++t) {
        const bool doL1 = (t < SEQ);
        const bool doL2 = (t >= 1);
        const int  s    = t - 1;     // L2 step

        // ---- issue all loads first (independent) ----
        const int tn2 = (t + 2 < SEQ) ? (t + 2) : (SEQ - 1);
        const float4 xv2 = __ldg(xb4 + tn2);

        const ulonglong2* h1v = reinterpret_cast<const ulonglong2*>(h1buf[(t + 1) & 1]); // h1(t-1)
        const ulonglong2* h2v = reinterpret_cast<const ulonglong2*>(
            h1buf[(t + 1) & 1]);  // L2 also reads h1(t-1) = h1(s)
        const ulonglong2* g2v = reinterpret_cast<const ulonglong2*>(h2buf[s & 1]);       // h2(s-1)

        // ---- L1 dot: 32 fma2 over 4 chains + x head ----
        ull a0 = fma2(xw0, pk2(xv.x, xv.y), bias1p);
        ull a1 = fma2(xw1, pk2(xv.z, xv.w), 0ull);
        ull a2 = 0ull, a3 = 0ull;
        // ---- L2 half-dot: 24 fma2 over 4 chains (independent of L1 chains) ----
        ull e0 = bias2p, e1 = 0ull, e2 = 0ull, e3 = 0ull;

        if (doL1) {
            #pragma unroll
            for (int kk = 0; kk < 8; ++kk) {
                const ulonglong2 hA = h1v[2 * kk];
                const ulonglong2 hB = h1v[2 * kk + 1];
                a0 = fma2(w1[4 * kk + 0], hA.x, a0);
                a1 = fma2(w1[4 * kk + 1], hA.y, a1);
                a2 = fma2(w1[4 * kk + 2], hB.x, a2);
                a3 = fma2(w1[4 * kk + 3], hB.y, a3);
            }
        }
        if (doL2) {
            const ulonglong2* hh = h2v + half * 8;   // this half's 32 h1 values
            #pragma unroll
            for (int kk = 0; kk < 4; ++kk) {
                const ulonglong2 hA = hh[2 * kk];
                const ulonglong2 hB = hh[2 * kk + 1];
                e0 = fma2(w2a[4 * kk + 0], hA.x, e0);
                e1 = fma2(w2a[4 * kk + 1], hA.y, e1);
                e2 = fma2(w2a[4 * kk + 2], hB.x, e2);
                e3 = fma2(w2a[4 * kk + 3], hB.y, e3);
            }
            const ulonglong2* gg = g2v + half * 4;   // this half's 16 h2 values
            #pragma unroll
            for (int kk = 0; kk < 2; ++kk) {
                const ulonglong2 hA = gg[2 * kk];
                const ulonglong2 hB = gg[2 * kk + 1];
                e0 = fma2(w2b[4 * kk + 0], hA.x, e0);
                e1 = fma2(w2b[4 * kk + 1], hA.y, e1);
                e2 = fma2(w2b[4 * kk + 2], hB.x, e2);
                e3 = fma2(w2b[4 * kk + 3], hB.y, e3);
            }
        }

        // ---- L2 tail (runs first: its shuffles overlap L1's reduction) ----
        float h2new = 0.0f;
        if (doL2) {
            e0 = add2(add2(e0, e1), add2(e2, e3));
            float lo, hi; upk2(e0, lo, hi);
            const float part = lo + hi;
            const float raw  = part + __shfl_xor_sync(0xffffffffu, part, 1);
            const float act  = __fmaf_rn(actA2, tanh_approx(raw), actB2);
            const float f2 = __shfl_xor_sync(0xffffffffu, act, 2);
            const float g2 = __shfl_xor_sync(0xffffffffu, act, 4);
            const float o2 = __shfl_xor_sync(0xffffffffu, act, 6);
            const float fc = f2 * c2;
            c2 = fc + act * g2;
            h2new = o2 * tanh_approx(c2);
        }

        // ---- L1 tail ----
        float h1new = 0.0f;
        if (doL1) {
            a0 = add2(add2(a0, a1), add2(a2, a3));
            float lo, hi; upk2(a0, lo, hi);
            const float raw = lo + hi;
            const float act = __fmaf_rn(actA1, tanh_approx(raw), actB1);
            const float v1 = __shfl_xor_sync(0xffffffffu, act, 1);
            const float v2 = __shfl_xor_sync(0xffffffffu, act, 2);
            const float v3 = __shfl_xor_sync(0xffffffffu, act, 3);
            const float fc = v1 * c1;
            c1 = fc + act * v2;
            h1new = v3 * tanh_approx(c1);
        }

        // ---- writes ----
        if (doL1 && q1 == 0) h1buf[t & 1][u1] = h1new;
        if (doL2 && (tid & 7) == 0) {
            const int u2 = tid >> 3;
            h2buf[(s + 1) & 1][u2] = h2new;
            outb[(size_t)s * H2 + u2] = h2new;
        }

        __syncthreads();
        xv = xv1; xv1 = xv2;
    }
}

extern "C" void kernel_launch(void* const* d_in, const int* in_sizes, int n_in,
                              void* d_out, int out_size) {
    const float* x     = (const float*)d_in[0];
    const float* W_ih1 = (const float*)d_in[1];
    const float* W_hh1 = (const float*)d_in[2];
    const float* b_ih1 = (const float*)d_in[3];
    const float* b_hh1 = (const float*)d_in[4];
    const float* W_ih2 = (const float*)d_in[5];
    const float* W_hh2 = (const float*)d_in[6];
    const float* b_ih2 = (const float*)d_in[7];
    const float* b_hh2 = (const float*)d_in[8];
    float* out = (float*)d_out;

    lstm2_kernel<<<BATCH, NTHREADS>>>(x, W_ih1, W_hh1, b_ih1, b_hh1,
                                      W_ih2, W_hh2, b_ih2, b_hh2, out);
}